// round 15
// baseline (speedup 1.0000x reference)
#include <cuda_runtime.h>
#include <cuda_fp16.h>
#include <cstdint>

// Problem constants (fixed by setup_inputs)
#define BATCH 4
#define SEQ   2048
#define EDIM  512
#define HNUM  8
#define RNUM  16
#define DDIM  64
#define TOK   (BATCH * SEQ)      // 8192 tokens
#define ERDIM (EDIM * RNUM)      // 8192 Wv rows

// K1/K4 (fp16, K=512, tile 64x128, BK=32)
#define NCH16   16
#define G_ROWB  80               // 64B data + 16B pad
#define G_AT    (64  * G_ROWB)   // 5120
#define G_BT    (128 * G_ROWB)   // 10240
#define G_STAGE (G_AT + G_BT)    // 15360

// K1-fused epilogue q-tile: 64 rows x 136 floats (16B-aligned rows)
#define QP      136
#define K1_SMEM (64 * QP * 4)    // 34816 > 2*G_STAGE (30720)

// K3 (fp16, K=512, tile 128x128, BK=64, 128 threads, 3-stage pipeline)
#define K7_NCH   8               // 512 / 64
#define K7_RX    144             // 128B data + 16B pad
#define K7_AT    (128 * K7_RX)   // 18432 (A tile == B tile)
#define K7_STAGE (2 * K7_AT)     // 36864
#define K7_SMEM  (3 * K7_STAGE)  // 110592 (3 stages; 2 CTAs/SM)

// Scratch (allocation-free: __device__ globals)
__device__ float g_attn[TOK * HNUM * RNUM];    // softmax over rules
__device__ float g_iw2[HNUM * RNUM * DDIM];    // 1 / rules_widths^2
__device__ __half g_Vh[(size_t)TOK   * EDIM];  // value  fp16
__device__ __half g_Qh[(size_t)TOK   * EDIM];  // query  fp16
__device__ __half g_Wvh[(size_t)ERDIM * EDIM]; // Wv     fp16
__device__ __half g_Wqh[(size_t)EDIM * EDIM];  // Wq     fp16
__device__ __half g_Woh[(size_t)EDIM * EDIM];  // Wo     fp16
__device__ __half g_Fh[(size_t)TOK   * EDIM];  // F fp16, (b,h,s,d) row order

// ---------------------------------------------------------------------------
// Portable PTX helpers (sm_80+)
// ---------------------------------------------------------------------------
__device__ __forceinline__ uint32_t smem_u32(const void* p) {
    uint32_t a;
    asm("{ .reg .u64 t; cvta.to.shared.u64 t, %1; cvt.u32.u64 %0, t; }"
        : "=r"(a) : "l"(p));
    return a;
}
__device__ __forceinline__ void cp_async16(uint32_t dst, const void* src) {
    asm volatile("cp.async.cg.shared.global [%0], [%1], 16;"
                 :: "r"(dst), "l"(src) : "memory");
}
__device__ __forceinline__ void ldmatrix_x4(uint32_t* r, uint32_t addr) {
    asm volatile("ldmatrix.sync.aligned.m8n8.x4.shared.b16 {%0,%1,%2,%3}, [%4];"
                 : "=r"(r[0]), "=r"(r[1]), "=r"(r[2]), "=r"(r[3]) : "r"(addr));
}
__device__ __forceinline__ void mma_fp16(float* c, const uint32_t* a,
                                         uint32_t b0, uint32_t b1) {
    asm volatile(
        "mma.sync.aligned.m16n8k16.row.col.f32.f16.f16.f32 "
        "{%0,%1,%2,%3}, {%4,%5,%6,%7}, {%8,%9}, {%0,%1,%2,%3};"
        : "+f"(c[0]), "+f"(c[1]), "+f"(c[2]), "+f"(c[3])
        : "r"(a[0]), "r"(a[1]), "r"(a[2]), "r"(a[3]), "r"(b0), "r"(b1));
}

// ---------------------------------------------------------------------------
// ONE merged preprocessing kernel: 5 fp32->fp16 converts + iw2.
// ---------------------------------------------------------------------------
#define N4_TOK  (TOK * EDIM / 4)     // 1048576
#define N4_WV   (ERDIM * EDIM / 4)   // 1048576
#define N4_W    (EDIM * EDIM / 4)    // 65536
#define R0 (N4_TOK)
#define R1 (2 * N4_TOK)
#define R2 (R1 + N4_WV)
#define R3 (R2 + N4_W)
#define R4 (R3 + N4_W)               // 3276800
#define PREP_GRID ((R4 + HNUM * RNUM * DDIM) / 256)   // 12832

__device__ __forceinline__ void conv4(const float* __restrict__ s,
                                      __half* __restrict__ d, size_t i) {
    float4 v = ((const float4*)s)[i];
    *(__half2*)(d + i * 4)     = __halves2half2(__float2half_rn(v.x), __float2half_rn(v.y));
    *(__half2*)(d + i * 4 + 2) = __halves2half2(__float2half_rn(v.z), __float2half_rn(v.w));
}

__global__ __launch_bounds__(256) void prep_all_kernel(
    const float* __restrict__ value, const float* __restrict__ query,
    const float* __restrict__ Wv, const float* __restrict__ Wq,
    const float* __restrict__ Wo, const float* __restrict__ rw)
{
    size_t i = (size_t)blockIdx.x * 256 + threadIdx.x;
    if      (i < R0) conv4(value, g_Vh,  i);
    else if (i < R1) conv4(query, g_Qh,  i - R0);
    else if (i < R2) conv4(Wv,    g_Wvh, i - R1);
    else if (i < R3) conv4(Wq,    g_Wqh, i - R2);
    else if (i < R4) conv4(Wo,    g_Woh, i - R3);
    else {
        int j = (int)(i - R4);            // 8192 iw2 elements
        float t = 1.0f / rw[j];
        g_iw2[j] = t * t;
    }
}

// ---------------------------------------------------------------------------
// K1 FUSED: q projection (HMMA, tile 64 tokens x 128 features = 2 full heads)
// + fuzzy rule attention computed in-CTA from the q tile in smem.
// No g_Q round-trip; writes only g_attn.
// ---------------------------------------------------------------------------
__global__ __launch_bounds__(256) void hmma_q_attn_kernel(
    const __half* __restrict__ A, const __half* __restrict__ B,
    const float* __restrict__ bq, const float* __restrict__ rk)
{
    __shared__ __align__(16) char smem[K1_SMEM];   // aliased: tiles | q-tile
    const uint32_t sbase = smem_u32(smem);

    const int tid    = threadIdx.x;
    const int lane   = tid & 31;
    const int wid    = tid >> 5;
    const int warp_m = wid & 1;     // 2 x 32 rows
    const int warp_n = wid >> 1;    // 4 x 32 cols
    const int m0     = blockIdx.y * 64;    // token base
    const int n0     = blockIdx.x * 128;   // feature base (2 heads)

    float acc[2][4][4] = {};

    auto load_chunk = [&](int c, int buf) {
        const uint32_t s0 = sbase + (uint32_t)buf * G_STAGE;
        {   // A: 64 rows x 4 x 16B
            const int row = tid >> 2;
            const int c16 = tid & 3;
            cp_async16(s0 + (uint32_t)row * G_ROWB + (uint32_t)c16 * 16,
                       A + (size_t)(m0 + row) * EDIM + c * 32 + c16 * 8);
        }
        #pragma unroll
        for (int t = 0; t < 2; t++) {  // B: 128 rows x 4 x 16B
            const int idx = tid + t * 256;
            const int row = idx >> 2;
            const int c16 = idx & 3;
            cp_async16(s0 + G_AT + (uint32_t)row * G_ROWB + (uint32_t)c16 * 16,
                       B + (size_t)(n0 + row) * EDIM + c * 32 + c16 * 8);
        }
        asm volatile("cp.async.commit_group;" ::: "memory");
    };

    const uint32_t lm_row = (uint32_t)(lane & 15);
    const uint32_t lm_kb  = (uint32_t)(lane >> 4) * 16;

    load_chunk(0, 0);

    for (int c = 0; c < NCH16; c++) {
        const int buf = c & 1;
        if (c + 1 < NCH16) {
            load_chunk(c + 1, buf ^ 1);
            asm volatile("cp.async.wait_group 1;" ::: "memory");
        } else {
            asm volatile("cp.async.wait_group 0;" ::: "memory");
        }
        __syncthreads();

        const uint32_t a_s = sbase + (uint32_t)buf * G_STAGE;
        const uint32_t b_s = a_s + G_AT;

        #pragma unroll
        for (int ks = 0; ks < 2; ks++) {
            const uint32_t kb = (uint32_t)ks * 32 + lm_kb;
            uint32_t afr[2][4];
            #pragma unroll
            for (int mt = 0; mt < 2; mt++) {
                const uint32_t row = (uint32_t)(warp_m * 32 + mt * 16) + lm_row;
                ldmatrix_x4(afr[mt], a_s + row * G_ROWB + kb);
            }
            uint32_t bfr[2][4];
            #pragma unroll
            for (int np = 0; np < 2; np++) {
                const uint32_t row = (uint32_t)(warp_n * 32 + np * 16) + lm_row;
                ldmatrix_x4(bfr[np], b_s + row * G_ROWB + kb);
            }
            #pragma unroll
            for (int mt = 0; mt < 2; mt++)
                #pragma unroll
                for (int nt = 0; nt < 4; nt++)
                    mma_fp16(acc[mt][nt], afr[mt],
                             bfr[nt >> 1][nt & 1], bfr[nt >> 1][(nt & 1) + 2]);
        }
        __syncthreads();
    }

    // -------- stage scaled q tile to smem (after final sync, tiles free) ----
    float* qt = (float*)smem;   // [64][QP]
    {
        const int q  = lane & 3;
        const int rg = lane >> 2;
        #pragma unroll
        for (int mt = 0; mt < 2; mt++) {
            #pragma unroll
            for (int half = 0; half < 2; half++) {
                const int rowl = warp_m * 32 + mt * 16 + rg + half * 8;
                #pragma unroll
                for (int nt = 0; nt < 4; nt++) {
                    const int col = warp_n * 32 + nt * 8 + q * 2;
                    float2 v;
                    v.x = (acc[mt][nt][half * 2 + 0] + __ldg(bq + n0 + col))     * 0.125f;
                    v.y = (acc[mt][nt][half * 2 + 1] + __ldg(bq + n0 + col + 1)) * 0.125f;
                    *(float2*)(qt + rowl * QP + col) = v;
                }
            }
        }
    }
    __syncthreads();

    // -------- fuzzy attention for 64 tokens x 2 heads --------
    // lanes 0-15: rules of head h0, lanes 16-31: rules of head h0+1.
    {
        const int hg = lane >> 4;       // 0/1
        const int r  = lane & 15;
        const int h  = (n0 >> 6) + hg;  // global head
        const float4* rk4 = (const float4*)(rk    + ((size_t)h * RNUM + r) * DDIM);
        const float4* iw4 = (const float4*)(g_iw2 + ((size_t)h * RNUM + r) * DDIM);

        #pragma unroll
        for (int it = 0; it < 8; it++) {
            const int tl = (wid << 3) + it;      // token-local 0..63
            const int t  = m0 + tl;
            const float4* qv4 = (const float4*)(qt + tl * QP + hg * 64);

            float z0 = 0.f, z1 = 0.f, z2 = 0.f, z3 = 0.f;
            #pragma unroll
            for (int dk = 0; dk < 16; dk++) {
                const float4 qv = qv4[dk];
                const float4 kv = __ldg(rk4 + dk);
                const float4 wv = __ldg(iw4 + dk);
                float d0 = qv.x - kv.x; z0 = fmaf(d0 * d0, wv.x, z0);
                float d1 = qv.y - kv.y; z1 = fmaf(d1 * d1, wv.y, z1);
                float d2 = qv.z - kv.z; z2 = fmaf(d2 * d2, wv.z, z2);
                float d3 = qv.w - kv.w; z3 = fmaf(d3 * d3, wv.w, z3);
            }
            float z = ((z0 + z1) + (z2 + z3)) * (-0.5f / DDIM);

            // softmax over the 16-lane rule group
            float mz = z;
            #pragma unroll
            for (int o = 8; o; o >>= 1)
                mz = fmaxf(mz, __shfl_xor_sync(0xffffffffu, mz, o));
            float e = expf(z - mz);
            float s = e;
            #pragma unroll
            for (int o = 8; o; o >>= 1)
                s += __shfl_xor_sync(0xffffffffu, s, o);
            g_attn[(size_t)t * (HNUM * RNUM) + h * RNUM + r] = e / s;
        }
    }
}

// ---------------------------------------------------------------------------
// K4: plain fp16 HMMA GEMM, K=512, tile 64x128, BK=32, double-buffered.
// ---------------------------------------------------------------------------
__global__ __launch_bounds__(256) void hmma_gemm16_kernel(
    const __half* __restrict__ A, const __half* __restrict__ B,
    const float* __restrict__ bias, float* __restrict__ C, float scale)
{
    __shared__ __align__(16) char smem[2 * G_STAGE];
    const uint32_t sbase = smem_u32(smem);

    const int tid    = threadIdx.x;
    const int lane   = tid & 31;
    const int wid    = tid >> 5;
    const int warp_m = wid & 1;
    const int warp_n = wid >> 1;
    const int m0     = blockIdx.y * 64;
    const int n0     = blockIdx.x * 128;

    float acc[2][4][4] = {};

    auto load_chunk = [&](int c, int buf) {
        const uint32_t s0 = sbase + (uint32_t)buf * G_STAGE;
        {
            const int row = tid >> 2;
            const int c16 = tid & 3;
            cp_async16(s0 + (uint32_t)row * G_ROWB + (uint32_t)c16 * 16,
                       A + (size_t)(m0 + row) * EDIM + c * 32 + c16 * 8);
        }
        #pragma unroll
        for (int t = 0; t < 2; t++) {
            const int idx = tid + t * 256;
            const int row = idx >> 2;
            const int c16 = idx & 3;
            cp_async16(s0 + G_AT + (uint32_t)row * G_ROWB + (uint32_t)c16 * 16,
                       B + (size_t)(n0 + row) * EDIM + c * 32 + c16 * 8);
        }
        asm volatile("cp.async.commit_group;" ::: "memory");
    };

    const uint32_t lm_row = (uint32_t)(lane & 15);
    const uint32_t lm_kb  = (uint32_t)(lane >> 4) * 16;

    load_chunk(0, 0);

    for (int c = 0; c < NCH16; c++) {
        const int buf = c & 1;
        if (c + 1 < NCH16) {
            load_chunk(c + 1, buf ^ 1);
            asm volatile("cp.async.wait_group 1;" ::: "memory");
        } else {
            asm volatile("cp.async.wait_group 0;" ::: "memory");
        }
        __syncthreads();

        const uint32_t a_s = sbase + (uint32_t)buf * G_STAGE;
        const uint32_t b_s = a_s + G_AT;

        #pragma unroll
        for (int ks = 0; ks < 2; ks++) {
            const uint32_t kb = (uint32_t)ks * 32 + lm_kb;
            uint32_t afr[2][4];
            #pragma unroll
            for (int mt = 0; mt < 2; mt++) {
                const uint32_t row = (uint32_t)(warp_m * 32 + mt * 16) + lm_row;
                ldmatrix_x4(afr[mt], a_s + row * G_ROWB + kb);
            }
            uint32_t bfr[2][4];
            #pragma unroll
            for (int np = 0; np < 2; np++) {
                const uint32_t row = (uint32_t)(warp_n * 32 + np * 16) + lm_row;
                ldmatrix_x4(bfr[np], b_s + row * G_ROWB + kb);
            }
            #pragma unroll
            for (int mt = 0; mt < 2; mt++)
                #pragma unroll
                for (int nt = 0; nt < 4; nt++)
                    mma_fp16(acc[mt][nt], afr[mt],
                             bfr[nt >> 1][nt & 1], bfr[nt >> 1][(nt & 1) + 2]);
        }
        __syncthreads();
    }

    const int q  = lane & 3;
    const int rg = lane >> 2;
    #pragma unroll
    for (int mt = 0; mt < 2; mt++) {
        #pragma unroll
        for (int half = 0; half < 2; half++) {
            const int row = m0 + warp_m * 32 + mt * 16 + rg + half * 8;
            #pragma unroll
            for (int nt = 0; nt < 4; nt++) {
                const int col = n0 + warp_n * 32 + nt * 8 + q * 2;
                float2 v;
                v.x = (acc[mt][nt][half * 2 + 0] + bias[col])     * scale;
                v.y = (acc[mt][nt][half * 2 + 1] + bias[col + 1]) * scale;
                *(float2*)(C + (size_t)row * EDIM + col) = v;
            }
        }
    }
}

// ---------------------------------------------------------------------------
// K3 v7: fp16 single-product GEMM + fused fuzzy epilogue (UNCHANGED, at the
// legacy-HMMA roof). Tile 128x128, 128 threads, BK=64, 3-stage pipeline.
// ---------------------------------------------------------------------------
__global__ void __launch_bounds__(128, 2) hmma_fused_v7_kernel(const float* __restrict__ bv)
{
    extern __shared__ __align__(16) char smem[];
    const uint32_t sbase = smem_u32(smem);

    const int tid    = threadIdx.x;
    const int lane   = tid & 31;
    const int wid    = tid >> 5;
    const int warp_m = wid & 1;     // 2 x 64 rows
    const int warp_n = wid >> 1;    // 2 x 64 cols
    const int m0     = blockIdx.y * 128;   // token base
    const int n0     = blockIdx.x * 128;   // Wv-row base

    float acc[4][8][4] = {};

    auto load_chunk = [&](int c, int buf) {
        const uint32_t s0 = sbase + (uint32_t)buf * K7_STAGE;
        #pragma unroll
        for (int i = 0; i < 8; i++) {
            const int idx = tid + i * 128;
            const int row = idx >> 3;
            const int c16 = idx & 7;
            cp_async16(s0 + (uint32_t)row * K7_RX + (uint32_t)c16 * 16,
                       g_Vh + (size_t)(m0 + row) * EDIM + c * 64 + c16 * 8);
        }
        #pragma unroll
        for (int i = 0; i < 8; i++) {
            const int idx = tid + i * 128;
            const int row = idx >> 3;
            const int c16 = idx & 7;
            cp_async16(s0 + K7_AT + (uint32_t)row * K7_RX + (uint32_t)c16 * 16,
                       g_Wvh + (size_t)(n0 + row) * EDIM + c * 64 + c16 * 8);
        }
        asm volatile("cp.async.commit_group;" ::: "memory");
    };

    const uint32_t lm_row = (uint32_t)(lane & 15);
    const uint32_t lm_kb  = (uint32_t)(lane >> 4) * 16;

    load_chunk(0, 0);
    load_chunk(1, 1);

    for (int c = 0; c < K7_NCH; c++) {
        if (c + 1 < K7_NCH) {
            asm volatile("cp.async.wait_group 1;" ::: "memory");
        } else {
            asm volatile("cp.async.wait_group 0;" ::: "memory");
        }
        __syncthreads();
        if (c + 2 < K7_NCH) load_chunk(c + 2, (c + 2) % 3);

        const uint32_t a_s = sbase + (uint32_t)(c % 3) * K7_STAGE;
        const uint32_t b_s = a_s + K7_AT;

        #pragma unroll
        for (int ks = 0; ks < 4; ks++) {
            const uint32_t kb = (uint32_t)ks * 32 + lm_kb;
            uint32_t afr[4][4];
            uint32_t bfr[4][4];
            #pragma unroll
            for (int nb = 0; nb < 4; nb++) {
                const uint32_t row = (uint32_t)(warp_n * 64 + nb * 16) + lm_row;
                ldmatrix_x4(bfr[nb], b_s + row * K7_RX + kb);
            }
            #pragma unroll
            for (int mt = 0; mt < 4; mt++) {
                const uint32_t row = (uint32_t)(warp_m * 64 + mt * 16) + lm_row;
                ldmatrix_x4(afr[mt], a_s + row * K7_RX + kb);
            }
            #pragma unroll
            for (int mt = 0; mt < 4; mt++)
                #pragma unroll
                for (int nt = 0; nt < 8; nt++)
                    mma_fp16(acc[mt][nt], afr[mt],
                             bfr[nt >> 1][nt & 1], bfr[nt >> 1][(nt & 1) + 2]);
        }
    }

    // -------- fused fuzzy epilogue (writes fp16 F) --------
    const int q   = lane & 3;
    const int rg  = lane >> 2;
    const int hd0 = n0 >> 4;
    const int h   = hd0 >> 6;
    const int d0c = hd0 & 63;

    float bvv[4][4];
    #pragma unroll
    for (int g = 0; g < 4; g++)
        #pragma unroll
        for (int ntl = 0; ntl < 2; ntl++)
            #pragma unroll
            for (int j = 0; j < 2; j++)
                bvv[g][ntl * 2 + j] =
                    __ldg(bv + n0 + warp_n * 64 + g * 16 + ntl * 8 + q * 2 + j);

    #pragma unroll
    for (int mt = 0; mt < 4; mt++) {
        #pragma unroll
        for (int half = 0; half < 2; half++) {
            const int rowm  = warp_m * 64 + mt * 16 + rg + half * 8;
            const int token = m0 + rowm;
            const int b     = token >> 11;
            const int s     = token & 2047;
            const float* ap = g_attn + (size_t)token * (HNUM * RNUM) + h * RNUM;
            const float at0 = ap[q * 2],     at1 = ap[q * 2 + 1];
            const float at2 = ap[q * 2 + 8], at3 = ap[q * 2 + 9];

            const int frow  = (b * HNUM + h) * 256 + (s >> 3);
            const int cbase = (s & 7) * 64;

            #pragma unroll
            for (int g = 0; g < 4; g++) {
                float p = (acc[mt][g * 2 + 0][half * 2 + 0] + bvv[g][0]) * at0
                        + (acc[mt][g * 2 + 0][half * 2 + 1] + bvv[g][1]) * at1
                        + (acc[mt][g * 2 + 1][half * 2 + 0] + bvv[g][2]) * at2
                        + (acc[mt][g * 2 + 1][half * 2 + 1] + bvv[g][3]) * at3;
                p += __shfl_down_sync(0xffffffffu, p, 2);
                p += __shfl_down_sync(0xffffffffu, p, 1);
                if (q == 0) {
                    p *= 0.125f;  // D^-0.5
                    const int col = cbase + d0c + warp_n * 4 + g;
                    g_Fh[(size_t)frow * EDIM + col] = __float2half_rn(p);
                }
            }
        }
    }
}

// ---------------------------------------------------------------------------
extern "C" void kernel_launch(void* const* d_in, const int* in_sizes, int n_in,
                              void* d_out, int out_size)
{
    const float* query = (const float*)d_in[0];
    // d_in[1] = key: unused by the reference computation
    const float* value = (const float*)d_in[2];
    const float* Wq    = (const float*)d_in[3];
    const float* bq    = (const float*)d_in[4];
    const float* Wv    = (const float*)d_in[5];
    const float* bv    = (const float*)d_in[6];
    const float* Wo    = (const float*)d_in[7];
    const float* bo    = (const float*)d_in[8];
    const float* rk    = (const float*)d_in[9];
    const float* rw    = (const float*)d_in[10];
    float* out = (float*)d_out;

    __half *Qh = nullptr, *Wqh = nullptr, *Woh = nullptr, *Fh = nullptr;
    cudaGetSymbolAddress((void**)&Qh,  g_Qh);
    cudaGetSymbolAddress((void**)&Wqh, g_Wqh);
    cudaGetSymbolAddress((void**)&Woh, g_Woh);
    cudaGetSymbolAddress((void**)&Fh,  g_Fh);

    cudaFuncSetAttribute(hmma_fused_v7_kernel,
                         cudaFuncAttributeMaxDynamicSharedMemorySize, K7_SMEM);

    dim3 blk(256);

    // 1: ALL preprocessing in one launch (5 converts + iw2)
    prep_all_kernel<<<dim3(PREP_GRID), blk>>>(value, query, Wv, Wq, Wo, rw);

    // 2: K1 q projection FUSED with fuzzy rule attention (writes g_attn only)
    hmma_q_attn_kernel<<<dim3(EDIM / 128, TOK / 64), blk>>>(Qh, Wqh, bq, rk);

    // 3: K3 fused v-GEMM + rule reduction (3-stage pipeline, at HMMA roof)
    hmma_fused_v7_kernel<<<dim3(ERDIM / 128, TOK / 128), dim3(128), K7_SMEM>>>(bv);

    // 4: K4 output projection (reads g_Fh directly)
    hmma_gemm16_kernel<<<dim3(EDIM / 128, TOK / 64), blk>>>(
        Fh, Woh, bo, out, 1.0f);
}

// round 16
// speedup vs baseline: 1.3692x; 1.3692x over previous
#include <cuda_runtime.h>
#include <cuda_fp16.h>
#include <cstdint>

// Problem constants (fixed by setup_inputs)
#define BATCH 4
#define SEQ   2048
#define EDIM  512
#define HNUM  8
#define RNUM  16
#define DDIM  64
#define TOK   (BATCH * SEQ)      // 8192 tokens
#define ERDIM (EDIM * RNUM)      // 8192 Wv rows

// K1/K4 (fp16, K=512, tile 128x128, BK=32) -- proven (R12/R13)
#define NCH16 16
#define ROWB  80                 // 64B data + 16B pad
#define TILEB (128 * ROWB)       // 10240

// K3 (fp16, K=512, tile 128x128, BK=64, 128 threads, warp tile 64x64) -- R13
#define K6_NCH   8               // 512 / 64
#define K6_RX    144             // 128B data + 16B pad
#define K6_AT    (128 * K6_RX)   // 18432
#define K6_STAGE (2 * K6_AT)     // 36864
#define K6_SMEM  (2 * K6_STAGE)  // 73728

// attn2 smem pitches (floats); 68*4=272B keeps 16B alignment, 2-way max conflict
#define QS_P 68

// Scratch (allocation-free: __device__ globals)
__device__ float g_Q[TOK * EDIM];              // scaled query projection (fp32)
__device__ float g_attn[TOK * HNUM * RNUM];    // softmax over rules
__device__ float g_iw2[HNUM * RNUM * DDIM];    // 1 / rules_widths^2
__device__ __half g_Vh[(size_t)TOK   * EDIM];  // value  fp16
__device__ __half g_Qh[(size_t)TOK   * EDIM];  // query  fp16
__device__ __half g_Wvh[(size_t)ERDIM * EDIM]; // Wv     fp16
__device__ __half g_Wqh[(size_t)EDIM * EDIM];  // Wq     fp16
__device__ __half g_Woh[(size_t)EDIM * EDIM];  // Wo     fp16
__device__ __half g_Fh[(size_t)TOK   * EDIM];  // F fp16, (b,h,s,d) row order

// ---------------------------------------------------------------------------
// Portable PTX helpers (sm_80+)
// ---------------------------------------------------------------------------
__device__ __forceinline__ uint32_t smem_u32(const void* p) {
    uint32_t a;
    asm("{ .reg .u64 t; cvta.to.shared.u64 t, %1; cvt.u32.u64 %0, t; }"
        : "=r"(a) : "l"(p));
    return a;
}
__device__ __forceinline__ void cp_async16(uint32_t dst, const void* src) {
    asm volatile("cp.async.cg.shared.global [%0], [%1], 16;"
                 :: "r"(dst), "l"(src) : "memory");
}
__device__ __forceinline__ void ldmatrix_x4(uint32_t* r, uint32_t addr) {
    asm volatile("ldmatrix.sync.aligned.m8n8.x4.shared.b16 {%0,%1,%2,%3}, [%4];"
                 : "=r"(r[0]), "=r"(r[1]), "=r"(r[2]), "=r"(r[3]) : "r"(addr));
}
__device__ __forceinline__ void mma_fp16(float* c, const uint32_t* a,
                                         uint32_t b0, uint32_t b1) {
    asm volatile(
        "mma.sync.aligned.m16n8k16.row.col.f32.f16.f16.f32 "
        "{%0,%1,%2,%3}, {%4,%5,%6,%7}, {%8,%9}, {%0,%1,%2,%3};"
        : "+f"(c[0]), "+f"(c[1]), "+f"(c[2]), "+f"(c[3])
        : "r"(a[0]), "r"(a[1]), "r"(a[2]), "r"(a[3]), "r"(b0), "r"(b1));
}

// ---------------------------------------------------------------------------
// Merged fp32 -> fp16 converts (float4 granularity) -- R13 proven.
// ---------------------------------------------------------------------------
#define N4_TOK  (TOK * EDIM / 4)     // 1048576
#define N4_WV   (ERDIM * EDIM / 4)   // 1048576
#define N4_W    (EDIM * EDIM / 4)    // 65536

__device__ __forceinline__ void conv4(const float* __restrict__ s,
                                      __half* __restrict__ d, size_t i) {
    float4 v = ((const float4*)s)[i];
    *(__half2*)(d + i * 4)     = __halves2half2(__float2half_rn(v.x), __float2half_rn(v.y));
    *(__half2*)(d + i * 4 + 2) = __halves2half2(__float2half_rn(v.z), __float2half_rn(v.w));
}

__global__ __launch_bounds__(256) void convA_kernel(
    const float* __restrict__ value, const float* __restrict__ query)
{
    size_t i = (size_t)blockIdx.x * 256 + threadIdx.x;
    if (i < N4_TOK) conv4(value, g_Vh, i);
    else            conv4(query, g_Qh, i - N4_TOK);
}

__global__ __launch_bounds__(256) void convB_kernel(
    const float* __restrict__ Wv, const float* __restrict__ Wq,
    const float* __restrict__ Wo)
{
    size_t i = (size_t)blockIdx.x * 256 + threadIdx.x;
    if (i < N4_WV)             conv4(Wv, g_Wvh, i);
    else if (i < N4_WV + N4_W) conv4(Wq, g_Wqh, i - N4_WV);
    else                       conv4(Wo, g_Woh, i - N4_WV - N4_W);
}

__global__ __launch_bounds__(256) void prep_iw2_kernel(const float* __restrict__ rw)
{
    int i = blockIdx.x * 256 + threadIdx.x;
    if (i < HNUM * RNUM * DDIM) {
        float t = 1.0f / rw[i];
        g_iw2[i] = t * t;
    }
}

// ---------------------------------------------------------------------------
// K2 v2: fuzzy rule attention, rule-tables cached in smem.
// Block = (64 tokens, 1 head). grid = (TOK/64, HNUM).
// Thread = (rule r = tid&15, token-slot ts = tid>>4); 4 tokens per thread
// (t = ts + 16*tt) so each rk/iw2 float4 is reused 4x from registers.
// Rule-table L2 traffic: 1024 blocks x 8.5KB = ~9MB (vs 512MB before).
// ---------------------------------------------------------------------------
__global__ __launch_bounds__(256) void attn2_kernel(const float* __restrict__ rk)
{
    __shared__ float qs [64][QS_P];     // q tile  (17408 B)
    __shared__ float rks[16][QS_P];     // rule keys
    __shared__ float iws[16][QS_P];     // rule inv-width^2

    const int tid = threadIdx.x;
    const int m0  = blockIdx.x * 64;    // token base
    const int h   = blockIdx.y;         // head

    // ---- load rules (1024 floats per table; 256 thr -> 1 float4 each) ----
    {
        const int r  = tid >> 4;        // 0..15
        const int d4 = tid & 15;        // 0..15
        const float4 kv = __ldg((const float4*)(rk    + ((size_t)h * RNUM + r) * DDIM) + d4);
        const float4 wv = __ldg((const float4*)(g_iw2 + ((size_t)h * RNUM + r) * DDIM) + d4);
        *(float4*)&rks[r][d4 * 4] = kv;
        *(float4*)&iws[r][d4 * 4] = wv;
    }
    // ---- load q tile: 64 tokens x 64 dims (head slice of g_Q) ----
    {
        const int t   = tid >> 2;       // 0..63
        const int d4l = tid & 3;        // 0..3 -> 4 float4 each
        const float4* src = (const float4*)(g_Q + (size_t)(m0 + t) * EDIM + h * DDIM);
        #pragma unroll
        for (int j = 0; j < 4; j++) {
            const int d4 = d4l * 4 + j;
            *(float4*)&qs[t][d4 * 4] = src[d4];
        }
    }
    __syncthreads();

    // ---- compute: 4 (token, rule) dots per thread ----
    const int r  = tid & 15;
    const int ts = tid >> 4;            // 0..15

    float z[4] = {0.f, 0.f, 0.f, 0.f};
    #pragma unroll
    for (int d4 = 0; d4 < 16; d4++) {
        const float4 kv = *(const float4*)&rks[r][d4 * 4];
        const float4 wv = *(const float4*)&iws[r][d4 * 4];
        #pragma unroll
        for (int tt = 0; tt < 4; tt++) {
            const float4 qv = *(const float4*)&qs[ts + 16 * tt][d4 * 4];
            float d0 = qv.x - kv.x;
            float d1 = qv.y - kv.y;
            float d2 = qv.z - kv.z;
            float d3 = qv.w - kv.w;
            z[tt] += d0 * d0 * wv.x + d1 * d1 * wv.y
                   + d2 * d2 * wv.z + d3 * d3 * wv.w;
        }
    }

    // ---- softmax over r (16 lanes = half-warp; xor<=8 stays inside) ----
    #pragma unroll
    for (int tt = 0; tt < 4; tt++) {
        float zz = z[tt] * (-0.5f / DDIM);
        float mz = zz;
        #pragma unroll
        for (int o = 8; o; o >>= 1)
            mz = fmaxf(mz, __shfl_xor_sync(0xffffffffu, mz, o));
        float e = expf(zz - mz);
        float s = e;
        #pragma unroll
        for (int o = 8; o; o >>= 1)
            s += __shfl_xor_sync(0xffffffffu, s, o);
        const int t = m0 + ts + 16 * tt;
        g_attn[(size_t)t * (HNUM * RNUM) + h * RNUM + r] = e / s;
    }
}

// ---------------------------------------------------------------------------
// K1/K4: plain fp16 HMMA GEMM, K=512, tile 128x128, double-buffered (proven).
// ---------------------------------------------------------------------------
__global__ __launch_bounds__(256) void hmma_gemm16_kernel(
    const __half* __restrict__ A, const __half* __restrict__ B,
    const float* __restrict__ bias, float* __restrict__ C, float scale)
{
    __shared__ __align__(16) char smem[4 * TILEB];
    const uint32_t sbase = smem_u32(smem);

    const int tid    = threadIdx.x;
    const int lane   = tid & 31;
    const int wid    = tid >> 5;
    const int warp_m = wid & 1;
    const int warp_n = wid >> 1;
    const int m0     = blockIdx.y * 128;
    const int n0     = blockIdx.x * 128;

    const int lrow = tid >> 2;
    const int lc16 = tid & 3;

    float acc[4][4][4] = {};

    auto load_chunk = [&](int c, int buf) {
        const uint32_t a_s = sbase + (uint32_t)buf * TILEB;
        const uint32_t b_s = sbase + 2u * TILEB + (uint32_t)buf * TILEB;
        #pragma unroll
        for (int t = 0; t < 2; t++) {
            const int row = lrow + t * 64;
            const uint32_t so = (uint32_t)row * ROWB + (uint32_t)lc16 * 16;
            cp_async16(a_s + so, A + (size_t)(m0 + row) * EDIM + c * 32 + lc16 * 8);
            cp_async16(b_s + so, B + (size_t)(n0 + row) * EDIM + c * 32 + lc16 * 8);
        }
        asm volatile("cp.async.commit_group;" ::: "memory");
    };

    const uint32_t lm_row = (uint32_t)(lane & 15);
    const uint32_t lm_kb  = (uint32_t)(lane >> 4) * 16;

    load_chunk(0, 0);

    for (int c = 0; c < NCH16; c++) {
        const int buf = c & 1;
        if (c + 1 < NCH16) {
            load_chunk(c + 1, buf ^ 1);
            asm volatile("cp.async.wait_group 1;" ::: "memory");
        } else {
            asm volatile("cp.async.wait_group 0;" ::: "memory");
        }
        __syncthreads();

        const uint32_t a_s = sbase + (uint32_t)buf * TILEB;
        const uint32_t b_s = sbase + 2u * TILEB + (uint32_t)buf * TILEB;

        #pragma unroll
        for (int ks = 0; ks < 2; ks++) {
            const uint32_t kb = (uint32_t)ks * 32 + lm_kb;
            uint32_t afr[4][4];
            #pragma unroll
            for (int mt = 0; mt < 4; mt++) {
                const uint32_t row = (uint32_t)(warp_m * 64 + mt * 16) + lm_row;
                ldmatrix_x4(afr[mt], a_s + row * ROWB + kb);
            }
            uint32_t bfr[2][4];
            #pragma unroll
            for (int np = 0; np < 2; np++) {
                const uint32_t row = (uint32_t)(warp_n * 32 + np * 16) + lm_row;
                ldmatrix_x4(bfr[np], b_s + row * ROWB + kb);
            }
            #pragma unroll
            for (int mt = 0; mt < 4; mt++)
                #pragma unroll
                for (int nt = 0; nt < 4; nt++)
                    mma_fp16(acc[mt][nt], afr[mt],
                             bfr[nt >> 1][nt & 1], bfr[nt >> 1][(nt & 1) + 2]);
        }
        __syncthreads();
    }

    const int q  = lane & 3;
    const int rg = lane >> 2;
    #pragma unroll
    for (int mt = 0; mt < 4; mt++) {
        #pragma unroll
        for (int half = 0; half < 2; half++) {
            const int row = m0 + warp_m * 64 + mt * 16 + rg + half * 8;
            #pragma unroll
            for (int nt = 0; nt < 4; nt++) {
                const int col = n0 + warp_n * 32 + nt * 8 + q * 2;
                float2 v;
                v.x = (acc[mt][nt][half * 2 + 0] + bias[col])     * scale;
                v.y = (acc[mt][nt][half * 2 + 1] + bias[col + 1]) * scale;
                *(float2*)(C + (size_t)row * EDIM + col) = v;
            }
        }
    }
}

// ---------------------------------------------------------------------------
// K3 v6: fp16 single-product GEMM + fused fuzzy epilogue (R13, at HMMA roof).
// Tile 128x128, 128 threads (2x2 warps, 64x64 each), BK=64, 2-stage.
// ---------------------------------------------------------------------------
__global__ void __launch_bounds__(128, 2) hmma_fused_v6_kernel(const float* __restrict__ bv)
{
    extern __shared__ __align__(16) char smem[];
    const uint32_t sbase = smem_u32(smem);

    const int tid    = threadIdx.x;
    const int lane   = tid & 31;
    const int wid    = tid >> 5;
    const int warp_m = wid & 1;
    const int warp_n = wid >> 1;
    const int m0     = blockIdx.y * 128;
    const int n0     = blockIdx.x * 128;

    float acc[4][8][4] = {};

    auto load_chunk = [&](int c, int buf) {
        const uint32_t s0 = sbase + (uint32_t)buf * K6_STAGE;
        #pragma unroll
        for (int i = 0; i < 8; i++) {
            const int idx = tid + i * 128;
            const int row = idx >> 3;
            const int c16 = idx & 7;
            cp_async16(s0 + (uint32_t)row * K6_RX + (uint32_t)c16 * 16,
                       g_Vh + (size_t)(m0 + row) * EDIM + c * 64 + c16 * 8);
        }
        #pragma unroll
        for (int i = 0; i < 8; i++) {
            const int idx = tid + i * 128;
            const int row = idx >> 3;
            const int c16 = idx & 7;
            cp_async16(s0 + K6_AT + (uint32_t)row * K6_RX + (uint32_t)c16 * 16,
                       g_Wvh + (size_t)(n0 + row) * EDIM + c * 64 + c16 * 8);
        }
        asm volatile("cp.async.commit_group;" ::: "memory");
    };

    const uint32_t lm_row = (uint32_t)(lane & 15);
    const uint32_t lm_kb  = (uint32_t)(lane >> 4) * 16;

    load_chunk(0, 0);

    for (int c = 0; c < K6_NCH; c++) {
        asm volatile("cp.async.wait_group 0;" ::: "memory");
        __syncthreads();
        if (c + 1 < K6_NCH) load_chunk(c + 1, (c + 1) & 1);

        const uint32_t a_s = sbase + (uint32_t)(c & 1) * K6_STAGE;
        const uint32_t b_s = a_s + K6_AT;

        #pragma unroll
        for (int ks = 0; ks < 4; ks++) {
            const uint32_t kb = (uint32_t)ks * 32 + lm_kb;
            uint32_t afr[4][4];
            uint32_t bfr[4][4];
            #pragma unroll
            for (int nb = 0; nb < 4; nb++) {
                const uint32_t row = (uint32_t)(warp_n * 64 + nb * 16) + lm_row;
                ldmatrix_x4(bfr[nb], b_s + row * K6_RX + kb);
            }
            #pragma unroll
            for (int mt = 0; mt < 4; mt++) {
                const uint32_t row = (uint32_t)(warp_m * 64 + mt * 16) + lm_row;
                ldmatrix_x4(afr[mt], a_s + row * K6_RX + kb);
            }
            #pragma unroll
            for (int mt = 0; mt < 4; mt++)
                #pragma unroll
                for (int nt = 0; nt < 8; nt++)
                    mma_fp16(acc[mt][nt], afr[mt],
                             bfr[nt >> 1][nt & 1], bfr[nt >> 1][(nt & 1) + 2]);
        }
    }

    // -------- fused fuzzy epilogue (writes fp16 F) --------
    const int q   = lane & 3;
    const int rg  = lane >> 2;
    const int hd0 = n0 >> 4;
    const int h   = hd0 >> 6;
    const int d0c = hd0 & 63;

    float bvv[4][4];
    #pragma unroll
    for (int g = 0; g < 4; g++)
        #pragma unroll
        for (int ntl = 0; ntl < 2; ntl++)
            #pragma unroll
            for (int j = 0; j < 2; j++)
                bvv[g][ntl * 2 + j] =
                    __ldg(bv + n0 + warp_n * 64 + g * 16 + ntl * 8 + q * 2 + j);

    #pragma unroll
    for (int mt = 0; mt < 4; mt++) {
        #pragma unroll
        for (int half = 0; half < 2; half++) {
            const int rowm  = warp_m * 64 + mt * 16 + rg + half * 8;
            const int token = m0 + rowm;
            const int b     = token >> 11;
            const int s     = token & 2047;
            const float* ap = g_attn + (size_t)token * (HNUM * RNUM) + h * RNUM;
            const float at0 = ap[q * 2],     at1 = ap[q * 2 + 1];
            const float at2 = ap[q * 2 + 8], at3 = ap[q * 2 + 9];

            const int frow  = (b * HNUM + h) * 256 + (s >> 3);
            const int cbase = (s & 7) * 64;

            #pragma unroll
            for (int g = 0; g < 4; g++) {
                float p = (acc[mt][g * 2 + 0][half * 2 + 0] + bvv[g][0]) * at0
                        + (acc[mt][g * 2 + 0][half * 2 + 1] + bvv[g][1]) * at1
                        + (acc[mt][g * 2 + 1][half * 2 + 0] + bvv[g][2]) * at2
                        + (acc[mt][g * 2 + 1][half * 2 + 1] + bvv[g][3]) * at3;
                p += __shfl_down_sync(0xffffffffu, p, 2);
                p += __shfl_down_sync(0xffffffffu, p, 1);
                if (q == 0) {
                    p *= 0.125f;  // D^-0.5
                    const int col = cbase + d0c + warp_n * 4 + g;
                    g_Fh[(size_t)frow * EDIM + col] = __float2half_rn(p);
                }
            }
        }
    }
}

// ---------------------------------------------------------------------------
extern "C" void kernel_launch(void* const* d_in, const int* in_sizes, int n_in,
                              void* d_out, int out_size)
{
    const float* query = (const float*)d_in[0];
    // d_in[1] = key: unused by the reference computation
    const float* value = (const float*)d_in[2];
    const float* Wq    = (const float*)d_in[3];
    const float* bq    = (const float*)d_in[4];
    const float* Wv    = (const float*)d_in[5];
    const float* bv    = (const float*)d_in[6];
    const float* Wo    = (const float*)d_in[7];
    const float* bo    = (const float*)d_in[8];
    const float* rk    = (const float*)d_in[9];
    const float* rw    = (const float*)d_in[10];
    float* out = (float*)d_out;

    float* Qp = nullptr;
    __half *Qh = nullptr, *Wqh = nullptr, *Woh = nullptr, *Fh = nullptr;
    cudaGetSymbolAddress((void**)&Qp,  g_Q);
    cudaGetSymbolAddress((void**)&Qh,  g_Qh);
    cudaGetSymbolAddress((void**)&Wqh, g_Wqh);
    cudaGetSymbolAddress((void**)&Woh, g_Woh);
    cudaGetSymbolAddress((void**)&Fh,  g_Fh);

    cudaFuncSetAttribute(hmma_fused_v6_kernel,
                         cudaFuncAttributeMaxDynamicSharedMemorySize, K6_SMEM);

    dim3 blk(256);

    // 1-3: preprocessing (R13 proven)
    convA_kernel<<<dim3((2 * N4_TOK) / 256), blk>>>(value, query);
    convB_kernel<<<dim3((N4_WV + 2 * N4_W) / 256), blk>>>(Wv, Wq, Wo);
    prep_iw2_kernel<<<dim3((HNUM * RNUM * DDIM + 255) / 256), blk>>>(rw);

    // 4: K1 q projection (scaled)
    hmma_gemm16_kernel<<<dim3(EDIM / 128, TOK / 128), blk>>>(
        Qh, Wqh, bq, Qp, 0.125f);

    // 5: K2 fuzzy rule attention (smem-cached rule tables)
    attn2_kernel<<<dim3(TOK / 64, HNUM), blk>>>(rk);

    // 6: K3 fused v-GEMM + rule reduction (64x64 warp tiles, at HMMA roof)
    hmma_fused_v6_kernel<<<dim3(ERDIM / 128, TOK / 128), dim3(128), K6_SMEM>>>(bv);

    // 7: K4 output projection (reads g_Fh directly)
    hmma_gemm16_kernel<<<dim3(EDIM / 128, TOK / 128), blk>>>(
        Fh, Woh, bo, out, 1.0f);
}

// round 17
// speedup vs baseline: 1.4018x; 1.0238x over previous
#include <cuda_runtime.h>
#include <cuda_fp16.h>
#include <cstdint>

// Problem constants (fixed by setup_inputs)
#define BATCH 4
#define SEQ   2048
#define EDIM  512
#define HNUM  8
#define RNUM  16
#define DDIM  64
#define TOK   (BATCH * SEQ)      // 8192 tokens
#define ERDIM (EDIM * RNUM)      // 8192 Wv rows

// Shared GEMM geometry (K=512, tile 128x128, BK=64, 128 threads, 64x64 warp
// tiles, 2-stage cp.async, 2 CTAs/SM) -- the proven K3-v6 skeleton.
#define KG_NCH   8               // 512 / 64
#define KG_RX    144             // 128B data + 16B pad
#define KG_AT    (128 * KG_RX)   // 18432
#define KG_STAGE (2 * KG_AT)     // 36864
#define KG_SMEM  (2 * KG_STAGE)  // 73728

// attn2 smem pitch (floats)
#define QS_P 68

// Scratch (allocation-free: __device__ globals)
__device__ float g_Q[TOK * EDIM];              // scaled query projection (fp32)
__device__ float g_attn[TOK * HNUM * RNUM];    // softmax over rules
__device__ float g_iw2[HNUM * RNUM * DDIM];    // 1 / rules_widths^2
__device__ __half g_Vh[(size_t)TOK   * EDIM];  // value  fp16
__device__ __half g_Qh[(size_t)TOK   * EDIM];  // query  fp16
__device__ __half g_Wvh[(size_t)ERDIM * EDIM]; // Wv     fp16
__device__ __half g_Wqh[(size_t)EDIM * EDIM];  // Wq     fp16
__device__ __half g_Woh[(size_t)EDIM * EDIM];  // Wo     fp16
__device__ __half g_Fh[(size_t)TOK   * EDIM];  // F fp16, (b,h,s,d) row order

// ---------------------------------------------------------------------------
// Portable PTX helpers (sm_80+)
// ---------------------------------------------------------------------------
__device__ __forceinline__ uint32_t smem_u32(const void* p) {
    uint32_t a;
    asm("{ .reg .u64 t; cvta.to.shared.u64 t, %1; cvt.u32.u64 %0, t; }"
        : "=r"(a) : "l"(p));
    return a;
}
__device__ __forceinline__ void cp_async16(uint32_t dst, const void* src) {
    asm volatile("cp.async.cg.shared.global [%0], [%1], 16;"
                 :: "r"(dst), "l"(src) : "memory");
}
__device__ __forceinline__ void ldmatrix_x4(uint32_t* r, uint32_t addr) {
    asm volatile("ldmatrix.sync.aligned.m8n8.x4.shared.b16 {%0,%1,%2,%3}, [%4];"
                 : "=r"(r[0]), "=r"(r[1]), "=r"(r[2]), "=r"(r[3]) : "r"(addr));
}
__device__ __forceinline__ void mma_fp16(float* c, const uint32_t* a,
                                         uint32_t b0, uint32_t b1) {
    asm volatile(
        "mma.sync.aligned.m16n8k16.row.col.f32.f16.f16.f32 "
        "{%0,%1,%2,%3}, {%4,%5,%6,%7}, {%8,%9}, {%0,%1,%2,%3};"
        : "+f"(c[0]), "+f"(c[1]), "+f"(c[2]), "+f"(c[3])
        : "r"(a[0]), "r"(a[1]), "r"(a[2]), "r"(a[3]), "r"(b0), "r"(b1));
}

// ---------------------------------------------------------------------------
// Merged fp32 -> fp16 converts (float4 granularity) -- proven.
// ---------------------------------------------------------------------------
#define N4_TOK  (TOK * EDIM / 4)     // 1048576
#define N4_WV   (ERDIM * EDIM / 4)   // 1048576
#define N4_W    (EDIM * EDIM / 4)    // 65536

__device__ __forceinline__ void conv4(const float* __restrict__ s,
                                      __half* __restrict__ d, size_t i) {
    float4 v = ((const float4*)s)[i];
    *(__half2*)(d + i * 4)     = __halves2half2(__float2half_rn(v.x), __float2half_rn(v.y));
    *(__half2*)(d + i * 4 + 2) = __halves2half2(__float2half_rn(v.z), __float2half_rn(v.w));
}

__global__ __launch_bounds__(256) void convA_kernel(
    const float* __restrict__ value, const float* __restrict__ query)
{
    size_t i = (size_t)blockIdx.x * 256 + threadIdx.x;
    if (i < N4_TOK) conv4(value, g_Vh, i);
    else            conv4(query, g_Qh, i - N4_TOK);
}

__global__ __launch_bounds__(256) void convB_kernel(
    const float* __restrict__ Wv, const float* __restrict__ Wq,
    const float* __restrict__ Wo)
{
    size_t i = (size_t)blockIdx.x * 256 + threadIdx.x;
    if (i < N4_WV)             conv4(Wv, g_Wvh, i);
    else if (i < N4_WV + N4_W) conv4(Wq, g_Wqh, i - N4_WV);
    else                       conv4(Wo, g_Woh, i - N4_WV - N4_W);
}

__global__ __launch_bounds__(256) void prep_iw2_kernel(const float* __restrict__ rw)
{
    int i = blockIdx.x * 256 + threadIdx.x;
    if (i < HNUM * RNUM * DDIM) {
        float t = 1.0f / rw[i];
        g_iw2[i] = t * t;
    }
}

// ---------------------------------------------------------------------------
// K2 v2: fuzzy rule attention, rule-tables cached in smem (R16 proven).
// ---------------------------------------------------------------------------
__global__ __launch_bounds__(256) void attn2_kernel(const float* __restrict__ rk)
{
    __shared__ float qs [64][QS_P];
    __shared__ float rks[16][QS_P];
    __shared__ float iws[16][QS_P];

    const int tid = threadIdx.x;
    const int m0  = blockIdx.x * 64;
    const int h   = blockIdx.y;

    {
        const int r  = tid >> 4;
        const int d4 = tid & 15;
        const float4 kv = __ldg((const float4*)(rk    + ((size_t)h * RNUM + r) * DDIM) + d4);
        const float4 wv = __ldg((const float4*)(g_iw2 + ((size_t)h * RNUM + r) * DDIM) + d4);
        *(float4*)&rks[r][d4 * 4] = kv;
        *(float4*)&iws[r][d4 * 4] = wv;
    }
    {
        const int t   = tid >> 2;
        const int d4l = tid & 3;
        const float4* src = (const float4*)(g_Q + (size_t)(m0 + t) * EDIM + h * DDIM);
        #pragma unroll
        for (int j = 0; j < 4; j++) {
            const int d4 = d4l * 4 + j;
            *(float4*)&qs[t][d4 * 4] = src[d4];
        }
    }
    __syncthreads();

    const int r  = tid & 15;
    const int ts = tid >> 4;

    float z[4] = {0.f, 0.f, 0.f, 0.f};
    #pragma unroll
    for (int d4 = 0; d4 < 16; d4++) {
        const float4 kv = *(const float4*)&rks[r][d4 * 4];
        const float4 wv = *(const float4*)&iws[r][d4 * 4];
        #pragma unroll
        for (int tt = 0; tt < 4; tt++) {
            const float4 qv = *(const float4*)&qs[ts + 16 * tt][d4 * 4];
            float d0 = qv.x - kv.x;
            float d1 = qv.y - kv.y;
            float d2 = qv.z - kv.z;
            float d3 = qv.w - kv.w;
            z[tt] += d0 * d0 * wv.x + d1 * d1 * wv.y
                   + d2 * d2 * wv.z + d3 * d3 * wv.w;
        }
    }

    #pragma unroll
    for (int tt = 0; tt < 4; tt++) {
        float zz = z[tt] * (-0.5f / DDIM);
        float mz = zz;
        #pragma unroll
        for (int o = 8; o; o >>= 1)
            mz = fmaxf(mz, __shfl_xor_sync(0xffffffffu, mz, o));
        float e = expf(zz - mz);
        float s = e;
        #pragma unroll
        for (int o = 8; o; o >>= 1)
            s += __shfl_xor_sync(0xffffffffu, s, o);
        const int t = m0 + ts + 16 * tt;
        g_attn[(size_t)t * (HNUM * RNUM) + h * RNUM + r] = e / s;
    }
}

// ---------------------------------------------------------------------------
// K1/K4 v2: plain fp16 HMMA GEMM on the v6 skeleton.
// Tile 128x128, 128 threads (2x2 warps, 64x64 each), BK=64, 2-stage,
// 2 CTAs/SM. C[m,n] = (A[m,:].B[n,:] + bias[n]) * scale, fp32 out.
// K-accumulation order identical to the previous version.
// ---------------------------------------------------------------------------
__global__ void __launch_bounds__(128, 2) hmma_gemm16_v2_kernel(
    const __half* __restrict__ A, const __half* __restrict__ B,
    const float* __restrict__ bias, float* __restrict__ C, float scale)
{
    extern __shared__ __align__(16) char smem[];
    const uint32_t sbase = smem_u32(smem);

    const int tid    = threadIdx.x;
    const int lane   = tid & 31;
    const int wid    = tid >> 5;
    const int warp_m = wid & 1;     // 2 x 64 rows
    const int warp_n = wid >> 1;    // 2 x 64 cols
    const int m0     = blockIdx.y * 128;
    const int n0     = blockIdx.x * 128;

    float acc[4][8][4] = {};

    auto load_chunk = [&](int c, int buf) {
        const uint32_t s0 = sbase + (uint32_t)buf * KG_STAGE;
        #pragma unroll
        for (int i = 0; i < 8; i++) {
            const int idx = tid + i * 128;
            const int row = idx >> 3;
            const int c16 = idx & 7;
            cp_async16(s0 + (uint32_t)row * KG_RX + (uint32_t)c16 * 16,
                       A + (size_t)(m0 + row) * EDIM + c * 64 + c16 * 8);
        }
        #pragma unroll
        for (int i = 0; i < 8; i++) {
            const int idx = tid + i * 128;
            const int row = idx >> 3;
            const int c16 = idx & 7;
            cp_async16(s0 + KG_AT + (uint32_t)row * KG_RX + (uint32_t)c16 * 16,
                       B + (size_t)(n0 + row) * EDIM + c * 64 + c16 * 8);
        }
        asm volatile("cp.async.commit_group;" ::: "memory");
    };

    const uint32_t lm_row = (uint32_t)(lane & 15);
    const uint32_t lm_kb  = (uint32_t)(lane >> 4) * 16;

    load_chunk(0, 0);

    for (int c = 0; c < KG_NCH; c++) {
        asm volatile("cp.async.wait_group 0;" ::: "memory");
        __syncthreads();
        if (c + 1 < KG_NCH) load_chunk(c + 1, (c + 1) & 1);

        const uint32_t a_s = sbase + (uint32_t)(c & 1) * KG_STAGE;
        const uint32_t b_s = a_s + KG_AT;

        #pragma unroll
        for (int ks = 0; ks < 4; ks++) {
            const uint32_t kb = (uint32_t)ks * 32 + lm_kb;
            uint32_t afr[4][4];
            uint32_t bfr[4][4];
            #pragma unroll
            for (int nb = 0; nb < 4; nb++) {
                const uint32_t row = (uint32_t)(warp_n * 64 + nb * 16) + lm_row;
                ldmatrix_x4(bfr[nb], b_s + row * KG_RX + kb);
            }
            #pragma unroll
            for (int mt = 0; mt < 4; mt++) {
                const uint32_t row = (uint32_t)(warp_m * 64 + mt * 16) + lm_row;
                ldmatrix_x4(afr[mt], a_s + row * KG_RX + kb);
            }
            #pragma unroll
            for (int mt = 0; mt < 4; mt++)
                #pragma unroll
                for (int nt = 0; nt < 8; nt++)
                    mma_fp16(acc[mt][nt], afr[mt],
                             bfr[nt >> 1][nt & 1], bfr[nt >> 1][(nt & 1) + 2]);
        }
    }

    // plain bias+scale epilogue (fp32 out, float2 stores)
    const int q  = lane & 3;
    const int rg = lane >> 2;
    #pragma unroll
    for (int mt = 0; mt < 4; mt++) {
        #pragma unroll
        for (int half = 0; half < 2; half++) {
            const int row = m0 + warp_m * 64 + mt * 16 + rg + half * 8;
            #pragma unroll
            for (int nt = 0; nt < 8; nt++) {
                const int col = n0 + warp_n * 64 + nt * 8 + q * 2;
                float2 v;
                v.x = (acc[mt][nt][half * 2 + 0] + __ldg(bias + col))     * scale;
                v.y = (acc[mt][nt][half * 2 + 1] + __ldg(bias + col + 1)) * scale;
                *(float2*)(C + (size_t)row * EDIM + col) = v;
            }
        }
    }
}

// ---------------------------------------------------------------------------
// K3 v6: fp16 single-product GEMM + fused fuzzy epilogue (at HMMA roof).
// ---------------------------------------------------------------------------
__global__ void __launch_bounds__(128, 2) hmma_fused_v6_kernel(const float* __restrict__ bv)
{
    extern __shared__ __align__(16) char smem[];
    const uint32_t sbase = smem_u32(smem);

    const int tid    = threadIdx.x;
    const int lane   = tid & 31;
    const int wid    = tid >> 5;
    const int warp_m = wid & 1;
    const int warp_n = wid >> 1;
    const int m0     = blockIdx.y * 128;
    const int n0     = blockIdx.x * 128;

    float acc[4][8][4] = {};

    auto load_chunk = [&](int c, int buf) {
        const uint32_t s0 = sbase + (uint32_t)buf * KG_STAGE;
        #pragma unroll
        for (int i = 0; i < 8; i++) {
            const int idx = tid + i * 128;
            const int row = idx >> 3;
            const int c16 = idx & 7;
            cp_async16(s0 + (uint32_t)row * KG_RX + (uint32_t)c16 * 16,
                       g_Vh + (size_t)(m0 + row) * EDIM + c * 64 + c16 * 8);
        }
        #pragma unroll
        for (int i = 0; i < 8; i++) {
            const int idx = tid + i * 128;
            const int row = idx >> 3;
            const int c16 = idx & 7;
            cp_async16(s0 + KG_AT + (uint32_t)row * KG_RX + (uint32_t)c16 * 16,
                       g_Wvh + (size_t)(n0 + row) * EDIM + c * 64 + c16 * 8);
        }
        asm volatile("cp.async.commit_group;" ::: "memory");
    };

    const uint32_t lm_row = (uint32_t)(lane & 15);
    const uint32_t lm_kb  = (uint32_t)(lane >> 4) * 16;

    load_chunk(0, 0);

    for (int c = 0; c < KG_NCH; c++) {
        asm volatile("cp.async.wait_group 0;" ::: "memory");
        __syncthreads();
        if (c + 1 < KG_NCH) load_chunk(c + 1, (c + 1) & 1);

        const uint32_t a_s = sbase + (uint32_t)(c & 1) * KG_STAGE;
        const uint32_t b_s = a_s + KG_AT;

        #pragma unroll
        for (int ks = 0; ks < 4; ks++) {
            const uint32_t kb = (uint32_t)ks * 32 + lm_kb;
            uint32_t afr[4][4];
            uint32_t bfr[4][4];
            #pragma unroll
            for (int nb = 0; nb < 4; nb++) {
                const uint32_t row = (uint32_t)(warp_n * 64 + nb * 16) + lm_row;
                ldmatrix_x4(bfr[nb], b_s + row * KG_RX + kb);
            }
            #pragma unroll
            for (int mt = 0; mt < 4; mt++) {
                const uint32_t row = (uint32_t)(warp_m * 64 + mt * 16) + lm_row;
                ldmatrix_x4(afr[mt], a_s + row * KG_RX + kb);
            }
            #pragma unroll
            for (int mt = 0; mt < 4; mt++)
                #pragma unroll
                for (int nt = 0; nt < 8; nt++)
                    mma_fp16(acc[mt][nt], afr[mt],
                             bfr[nt >> 1][nt & 1], bfr[nt >> 1][(nt & 1) + 2]);
        }
    }

    // -------- fused fuzzy epilogue (writes fp16 F) --------
    const int q   = lane & 3;
    const int rg  = lane >> 2;
    const int hd0 = n0 >> 4;
    const int h   = hd0 >> 6;
    const int d0c = hd0 & 63;

    float bvv[4][4];
    #pragma unroll
    for (int g = 0; g < 4; g++)
        #pragma unroll
        for (int ntl = 0; ntl < 2; ntl++)
            #pragma unroll
            for (int j = 0; j < 2; j++)
                bvv[g][ntl * 2 + j] =
                    __ldg(bv + n0 + warp_n * 64 + g * 16 + ntl * 8 + q * 2 + j);

    #pragma unroll
    for (int mt = 0; mt < 4; mt++) {
        #pragma unroll
        for (int half = 0; half < 2; half++) {
            const int rowm  = warp_m * 64 + mt * 16 + rg + half * 8;
            const int token = m0 + rowm;
            const int b     = token >> 11;
            const int s     = token & 2047;
            const float* ap = g_attn + (size_t)token * (HNUM * RNUM) + h * RNUM;
            const float at0 = ap[q * 2],     at1 = ap[q * 2 + 1];
            const float at2 = ap[q * 2 + 8], at3 = ap[q * 2 + 9];

            const int frow  = (b * HNUM + h) * 256 + (s >> 3);
            const int cbase = (s & 7) * 64;

            #pragma unroll
            for (int g = 0; g < 4; g++) {
                float p = (acc[mt][g * 2 + 0][half * 2 + 0] + bvv[g][0]) * at0
                        + (acc[mt][g * 2 + 0][half * 2 + 1] + bvv[g][1]) * at1
                        + (acc[mt][g * 2 + 1][half * 2 + 0] + bvv[g][2]) * at2
                        + (acc[mt][g * 2 + 1][half * 2 + 1] + bvv[g][3]) * at3;
                p += __shfl_down_sync(0xffffffffu, p, 2);
                p += __shfl_down_sync(0xffffffffu, p, 1);
                if (q == 0) {
                    p *= 0.125f;  // D^-0.5
                    const int col = cbase + d0c + warp_n * 4 + g;
                    g_Fh[(size_t)frow * EDIM + col] = __float2half_rn(p);
                }
            }
        }
    }
}

// ---------------------------------------------------------------------------
extern "C" void kernel_launch(void* const* d_in, const int* in_sizes, int n_in,
                              void* d_out, int out_size)
{
    const float* query = (const float*)d_in[0];
    // d_in[1] = key: unused by the reference computation
    const float* value = (const float*)d_in[2];
    const float* Wq    = (const float*)d_in[3];
    const float* bq    = (const float*)d_in[4];
    const float* Wv    = (const float*)d_in[5];
    const float* bv    = (const float*)d_in[6];
    const float* Wo    = (const float*)d_in[7];
    const float* bo    = (const float*)d_in[8];
    const float* rk    = (const float*)d_in[9];
    const float* rw    = (const float*)d_in[10];
    float* out = (float*)d_out;

    float* Qp = nullptr;
    __half *Qh = nullptr, *Wqh = nullptr, *Woh = nullptr, *Fh = nullptr;
    cudaGetSymbolAddress((void**)&Qp,  g_Q);
    cudaGetSymbolAddress((void**)&Qh,  g_Qh);
    cudaGetSymbolAddress((void**)&Wqh, g_Wqh);
    cudaGetSymbolAddress((void**)&Woh, g_Woh);
    cudaGetSymbolAddress((void**)&Fh,  g_Fh);

    cudaFuncSetAttribute(hmma_fused_v6_kernel,
                         cudaFuncAttributeMaxDynamicSharedMemorySize, KG_SMEM);
    cudaFuncSetAttribute(hmma_gemm16_v2_kernel,
                         cudaFuncAttributeMaxDynamicSharedMemorySize, KG_SMEM);

    dim3 blk(256);

    // 1-3: preprocessing (proven)
    convA_kernel<<<dim3((2 * N4_TOK) / 256), blk>>>(value, query);
    convB_kernel<<<dim3((N4_WV + 2 * N4_W) / 256), blk>>>(Wv, Wq, Wo);
    prep_iw2_kernel<<<dim3((HNUM * RNUM * DDIM + 255) / 256), blk>>>(rw);

    // 4: K1 q projection (scaled) on the v6 skeleton
    hmma_gemm16_v2_kernel<<<dim3(EDIM / 128, TOK / 128), dim3(128), KG_SMEM>>>(
        Qh, Wqh, bq, Qp, 0.125f);

    // 5: K2 fuzzy rule attention (smem-cached rule tables)
    attn2_kernel<<<dim3(TOK / 64, HNUM), blk>>>(rk);

    // 6: K3 fused v-GEMM + rule reduction (at HMMA roof)
    hmma_fused_v6_kernel<<<dim3(ERDIM / 128, TOK / 128), dim3(128), KG_SMEM>>>(bv);

    // 7: K4 output projection on the v6 skeleton (reads g_Fh directly)
    hmma_gemm16_v2_kernel<<<dim3(EDIM / 128, TOK / 128), dim3(128), KG_SMEM>>>(
        Fh, Woh, bo, out, 1.0f);
}